// round 14
// baseline (speedup 1.0000x reference)
#include <cuda_runtime.h>
#include <cuda_fp16.h>
#include <math.h>
#include <stdint.h>

#define NB 8
#define NT 512
#define NTOK 4096

// ===================== helpers =============================================
__device__ __forceinline__ uint32_t smem_to_u32(const void* p) {
    uint32_t a;
    asm("{ .reg .u64 t; cvta.to.shared.u64 t, %1; cvt.u32.u64 %0, t; }" : "=r"(a) : "l"(p));
    return a;
}
__device__ __forceinline__ void cp16(uint32_t s, const void* g) {
    asm volatile("cp.async.cg.shared.global [%0], [%1], 16;" :: "r"(s), "l"(g));
}
#define CP_COMMIT() asm volatile("cp.async.commit_group;" ::: "memory")
#define CP_WAIT(n)  asm volatile("cp.async.wait_group %0;" :: "n"(n) : "memory")

__device__ __forceinline__ void ldm4(uint32_t* r, uint32_t addr) {
    asm volatile("ldmatrix.sync.aligned.m8n8.x4.shared.b16 {%0,%1,%2,%3}, [%4];"
        : "=r"(r[0]), "=r"(r[1]), "=r"(r[2]), "=r"(r[3]) : "r"(addr));
}
__device__ __forceinline__ void mma16816(float* c, const uint32_t* a, const uint32_t* b) {
    asm volatile("mma.sync.aligned.m16n8k16.row.col.f32.f16.f16.f32 "
        "{%0,%1,%2,%3}, {%4,%5,%6,%7}, {%8,%9}, {%0,%1,%2,%3};"
        : "+f"(c[0]), "+f"(c[1]), "+f"(c[2]), "+f"(c[3])
        : "r"(a[0]), "r"(a[1]), "r"(a[2]), "r"(a[3]), "r"(b[0]), "r"(b[1]));
}

// ===================== device scratch ======================================
__device__ float g_tmp[NTOK * 1024];
__device__ float g_xz [NTOK * 2048];   // [x_ssm | silu(gate)]
__device__ float g_dt [NTOK * 1024];
__device__ float g_bc [NTOK * 32];     // interleaved: (B_n, C_n) pairs
__device__ float g_y  [NTOK * 1024];

__device__ __half a_emb[NTOK*1024];
__device__ __half a_x  [NTOK*1024];
__device__ __half a_ssm[NTOK*1024];
__device__ __half a_det[NTOK*1024];
__device__ __half a_h1 [NTOK*2048];    // [pr1 hidden | po1 hidden]
__device__ __half a_h2 [NTOK*2048];    // after lnsilu

// Weights: single fp16, transposed [N,K]
__device__ __half wt_emb [1024*1024];
__device__ __half wt_in  [2048*1024];
__device__ __half wt_dtbc[1152*1024];  // dt rows 0-1023, B/C 1024-1055, zeros above
__device__ __half wt_pr1 [1024*1024];
__device__ __half wt_pr2 [1024*1024];
__device__ __half wt_po1 [1024*2048];  // [N=1024, K=2048]
__device__ __half wt_po2 [1024*1024];

// ===================== HMMA GEMM (single-pass fp16) ========================
// Tile 256(M)x128(N), 8 warps (warp tile 64x64, 4x2), BK=32, 4 stages,
// 1 CTA/SM (smem-bound). Prefetch s+3 issued BEFORE compute(s).
// act: 0 none, 1 softplus, 2 silu on cols>=1024, 3 dt|bc split.
// Stage layout (80B-padded rows): A 256x80 @ +0, B 128x80 @ +20480.
#define STG_BYTES 30720
#define GEMM_SMEM (4*STG_BYTES + 512)

struct GemmArgs {
    const __half* A0; int K0;          // A cols [0,K0) from A0, rest from A1
    const __half* A1;
    int lda;
    const __half* B;
    const float* bias; int biasN;
    const float* addend; int ldadd;
    float* C; int ldc; int nvalid;
    __half* Chi; int ldhl;
    float* bc;                          // act==3 target for cols 1024-1055
    int K; int act;
};

__device__ __forceinline__ void gemm_impl(const GemmArgs a, char* smem)
{
    const uint32_t sb = smem_to_u32(smem);
    const int tid = threadIdx.x;
    const int lane = tid & 31, w = tid >> 5;
    const int bm = blockIdx.y * 256;
    const int bn = blockIdx.x * 128;
    const int wm = (w & 3) * 64;
    const int wn = (w >> 2) * 64;
    float* sbias = (float*)(smem + 4 * STG_BYTES);
    if (tid < 128) sbias[tid] = (a.bias && bn + tid < a.biasN) ? a.bias[bn + tid] : 0.f;

    const int nst = a.K >> 5;

    auto load_stage = [&](int s) {
        const uint32_t dst = sb + (uint32_t)(s & 3) * STG_BYTES;
        const int kglob = s << 5;
        #pragma unroll
        for (int j = 0; j < 6; j++) {
            int q = tid + (j << 8);          // 0..1535
            uint32_t d;
            const __half* src;
            if (q < 1024) {                  // A: 256 rows x 4 chunks
                int row = q >> 2, kc = q & 3;
                int col = kglob + kc * 8;
                const __half* base = a.A0;
                if (col >= a.K0) { base = a.A1; col -= a.K0; }
                d = dst + (uint32_t)(row * 80 + kc * 16);
                src = base + (size_t)(bm + row) * a.lda + col;
            } else {                         // B: 128 rows x 4 chunks
                int q2 = q - 1024;
                int row = q2 >> 2, kc = q2 & 3;
                d = dst + 20480u + (uint32_t)(row * 80 + kc * 16);
                src = a.B + (size_t)(bn + row) * a.K + kglob + kc * 8;
            }
            cp16(d, src);
        }
        CP_COMMIT();
    };

    load_stage(0); load_stage(1); load_stage(2);

    float acc[4][8][4] = {};

    for (int s = 0; s < nst; s++) {
        CP_WAIT(2);            // stage s resident (s+1, s+2 may be pending)
        __syncthreads();
        // prefetch s+3 BEFORE compute: buffer (s+3)&3 == (s-1)&3, whose readers
        // (compute(s-1)) all finished before the barrier above.
        if (s + 3 < nst) load_stage(s + 3); else CP_COMMIT();
        const uint32_t sA = sb + (uint32_t)(s & 3) * STG_BYTES;
        #pragma unroll
        for (int kk = 0; kk < 2; kk++) {
            const int kloc = kk * 16;
            uint32_t ah[4][4], bb[4][4];
            #pragma unroll
            for (int mi = 0; mi < 4; mi++) {
                uint32_t ad = sA
                    + (uint32_t)((wm + mi * 16 + (lane & 15)) * 80)
                    + (uint32_t)((kloc + ((lane >> 4) << 3)) * 2);
                ldm4(ah[mi], ad);
            }
            #pragma unroll
            for (int nj = 0; nj < 4; nj++) {
                uint32_t bd = sA + 20480u
                    + (uint32_t)((wn + nj * 16 + ((lane >> 4) << 3) + (lane & 7)) * 80)
                    + (uint32_t)((kloc + ((lane >> 3) & 1) * 8) * 2);
                ldm4(bb[nj], bd);
            }
            #pragma unroll
            for (int mi = 0; mi < 4; mi++)
                #pragma unroll
                for (int ns = 0; ns < 8; ns++)
                    mma16816(acc[mi][ns], ah[mi], &bb[ns >> 1][(ns & 1) * 2]);
        }
    }

    // ---- epilogue ----
    const int g = lane >> 2, cc = (lane & 3) * 2;
    const bool dohl = (a.Chi != nullptr) && (bn < a.ldhl);
    #pragma unroll
    for (int mi = 0; mi < 4; mi++) {
        #pragma unroll
        for (int r = 0; r < 2; r++) {
            const int m = bm + wm + mi * 16 + g + r * 8;
            #pragma unroll
            for (int ns = 0; ns < 8; ns++) {
                const int ncol = wn + ns * 8 + cc;
                const int n = bn + ncol;
                float v0 = acc[mi][ns][r * 2 + 0] + sbias[ncol];
                float v1 = acc[mi][ns][r * 2 + 1] + sbias[ncol + 1];
                if (a.act == 3) {
                    if (n < 1024) {
                        v0 = fmaxf(v0, 0.f) + log1pf(__expf(-fabsf(v0)));
                        v1 = fmaxf(v1, 0.f) + log1pf(__expf(-fabsf(v1)));
                        *(float2*)(a.C + (size_t)m * a.ldc + n) = make_float2(v0, v1);
                    } else if (n < 1056) {
                        *(float2*)(a.bc + (size_t)m * 32 + (n - 1024)) = make_float2(v0, v1);
                    }
                    continue;
                }
                if (a.addend) {
                    float2 ad = *(const float2*)(a.addend + (size_t)m * a.ldadd + n);
                    v0 += ad.x; v1 += ad.y;
                }
                if (a.act == 1) {
                    v0 = fmaxf(v0, 0.f) + log1pf(__expf(-fabsf(v0)));
                    v1 = fmaxf(v1, 0.f) + log1pf(__expf(-fabsf(v1)));
                } else if (a.act == 2 && n >= 1024) {
                    v0 = v0 * (1.f / (1.f + __expf(-v0)));
                    v1 = v1 * (1.f / (1.f + __expf(-v1)));
                }
                if (a.C && n < a.nvalid)
                    *(float2*)(a.C + (size_t)m * a.ldc + n) = make_float2(v0, v1);
                if (dohl) {
                    *(__half2*)(a.Chi + (size_t)m * a.ldhl + n) =
                        __halves2half2(__float2half_rn(v0), __float2half_rn(v1));
                }
            }
        }
    }
}

__global__ __launch_bounds__(256, 1) void gemm_one(GemmArgs a) {
    extern __shared__ char smem[];
    gemm_impl(a, smem);
}
__global__ __launch_bounds__(256, 1) void gemm_dual(GemmArgs a0, GemmArgs a1) {
    extern __shared__ char smem[];
    gemm_impl(blockIdx.z ? a1 : a0, smem);
}

// ===================== batched weight transpose -> fp16 ====================
// Transposes a 1024(K) x 1024(N) block of W[.., srcN] into Wt[N, dstK]+koff.
struct WSeg { const float* W; __half* H; int srcN; int dstK; int koff; };
struct WSegs { WSeg s[9]; };
__global__ __launch_bounds__(256) void wconv_multi(WSegs ws)
{
    __shared__ float s[32][33];
    const WSeg seg = ws.s[blockIdx.z];
    const int tx = threadIdx.x, ty = threadIdx.y;
    const int n0 = blockIdx.x * 32, k0 = blockIdx.y * 32;
    #pragma unroll
    for (int j = 0; j < 4; j++)
        s[ty + j * 8][tx] = seg.W[(size_t)(k0 + ty + j * 8) * seg.srcN + n0 + tx];
    __syncthreads();
    #pragma unroll
    for (int j = 0; j < 4; j++) {
        float v = s[tx][ty + j * 8];
        size_t o = (size_t)(n0 + ty + j * 8) * seg.dstK + seg.koff + k0 + tx;
        seg.H[o] = __float2half_rn(v);
    }
}

// ===================== pack W_B|W_C interleaved into wt_dtbc rows 1024+ ====
__global__ __launch_bounds__(256) void bcconv_kernel(
    const float* __restrict__ WB, const float* __restrict__ WC,
    __half* __restrict__ H)
{
    int id = blockIdx.x * 256 + threadIdx.x;   // 32768 total
    int j = id & 31, k = id >> 5;
    float v = (j & 1) ? WC[k * 16 + (j >> 1)] : WB[k * 16 + (j >> 1)];
    H[(size_t)(1024 + j) * 1024 + k] = __float2half_rn(v);
}

// ===================== embeds: [B,T]->[T,B] gather + fp16 ==================
__global__ __launch_bounds__(256) void aconv_kernel(
    const float* __restrict__ X, __half* __restrict__ H)
{
    const int p = blockIdx.x;
    const int src = (p & 7) * NT + (p >> 3);
    const int c = threadIdx.x * 4;
    float4 v = *(const float4*)(X + (size_t)src * 1024 + c);
    ((__half2*)(H + (size_t)p * 1024 + c))[0] =
        __halves2half2(__float2half_rn(v.x), __float2half_rn(v.y));
    ((__half2*)(H + (size_t)p * 1024 + c))[1] =
        __halves2half2(__float2half_rn(v.z), __float2half_rn(v.w));
}

// ===================== stage 0: lnsilu(actions @ W_pre + b) -> fp32 ========
__global__ __launch_bounds__(256) void pre_kernel(
    const float* __restrict__ actions, const float* __restrict__ W_pre,
    const float* __restrict__ b_pre, const float* __restrict__ g_pre,
    const float* __restrict__ bb_pre, float* __restrict__ xout)
{
    int p = blockIdx.x;
    int t = p >> 3, b = p & 7;
    __shared__ float sa[32];
    __shared__ float red[2][8];
    int tid = threadIdx.x;
    if (tid < 32) sa[tid] = actions[(size_t)(b * NT + t) * 32 + tid];
    __syncthreads();
    int c0 = tid * 4;
    float4 acc = *(const float4*)(b_pre + c0);
    #pragma unroll 8
    for (int k = 0; k < 32; k++) {
        float aa = sa[k];
        float4 wv = *(const float4*)(W_pre + (size_t)k * 1024 + c0);
        acc.x = fmaf(aa, wv.x, acc.x); acc.y = fmaf(aa, wv.y, acc.y);
        acc.z = fmaf(aa, wv.z, acc.z); acc.w = fmaf(aa, wv.w, acc.w);
    }
    float s  = acc.x + acc.y + acc.z + acc.w;
    float s2 = acc.x*acc.x + acc.y*acc.y + acc.z*acc.z + acc.w*acc.w;
    #pragma unroll
    for (int o = 16; o; o >>= 1) {
        s  += __shfl_xor_sync(0xffffffffu, s, o);
        s2 += __shfl_xor_sync(0xffffffffu, s2, o);
    }
    if ((tid & 31) == 0) { red[0][tid >> 5] = s; red[1][tid >> 5] = s2; }
    __syncthreads();
    if (tid == 0) {
        float aa = 0.f, c = 0.f;
        for (int i = 0; i < 8; i++) { aa += red[0][i]; c += red[1][i]; }
        red[0][0] = aa; red[1][0] = c;
    }
    __syncthreads();
    float mean = red[0][0] * (1.f / 1024.f);
    float var  = red[1][0] * (1.f / 1024.f) - mean * mean;
    float inv  = rsqrtf(var + 1e-5f);
    float vv[4] = {acc.x, acc.y, acc.z, acc.w};
    #pragma unroll
    for (int j = 0; j < 4; j++) {
        int c = c0 + j;
        float xn = (vv[j] - mean) * inv * g_pre[c] + bb_pre[c];
        xn = xn * (1.f / (1.f + __expf(-xn)));
        xout[(size_t)p * 1024 + c] = xn;
    }
}

// ===================== LayerNorm fp32-in -> fp32 + fp16 ====================
__global__ __launch_bounds__(256) void ln_kernel(
    const float* __restrict__ X,
    const float* __restrict__ gma, const float* __restrict__ bta,
    float* __restrict__ Y, int ldy,
    __half* __restrict__ H, int dosilu)
{
    int p = blockIdx.x;
    int tid = threadIdx.x;
    int c0 = tid * 4;
    __shared__ float red[2][8];
    float4 v = *(const float4*)(X + (size_t)p * 1024 + c0);
    float s  = v.x + v.y + v.z + v.w;
    float s2 = v.x*v.x + v.y*v.y + v.z*v.z + v.w*v.w;
    #pragma unroll
    for (int o = 16; o; o >>= 1) {
        s  += __shfl_xor_sync(0xffffffffu, s, o);
        s2 += __shfl_xor_sync(0xffffffffu, s2, o);
    }
    if ((tid & 31) == 0) { red[0][tid >> 5] = s; red[1][tid >> 5] = s2; }
    __syncthreads();
    if (tid == 0) {
        float aa = 0.f, c = 0.f;
        for (int i = 0; i < 8; i++) { aa += red[0][i]; c += red[1][i]; }
        red[0][0] = aa; red[1][0] = c;
    }
    __syncthreads();
    float mean = red[0][0] * (1.f / 1024.f);
    float var  = red[1][0] * (1.f / 1024.f) - mean * mean;
    float inv  = rsqrtf(var + 1e-5f);
    float vv[4] = {v.x, v.y, v.z, v.w};
    float xn[4];
    #pragma unroll
    for (int j = 0; j < 4; j++) {
        int c = c0 + j;
        float x = (vv[j] - mean) * inv * gma[c] + bta[c];
        if (dosilu) x = x * (1.f / (1.f + __expf(-x)));
        xn[j] = x;
    }
    if (Y) {
        #pragma unroll
        for (int j = 0; j < 4; j++) Y[(size_t)p * ldy + c0 + j] = xn[j];
    }
    if (H) {
        ((__half2*)(H + (size_t)p * 1024 + c0))[0] =
            __halves2half2(__float2half_rn(xn[0]), __float2half_rn(xn[1]));
        ((__half2*)(H + (size_t)p * 1024 + c0))[1] =
            __halves2half2(__float2half_rn(xn[2]), __float2half_rn(xn[3]));
    }
}

// ===================== batched head LN: fp16 in/out, +silu =================
__global__ __launch_bounds__(256) void ln16_kernel(
    const __half* __restrict__ Xin,
    const float* __restrict__ g0, const float* __restrict__ b0,
    const float* __restrict__ g1, const float* __restrict__ b1,
    __half* __restrict__ Yout)
{
    int p = blockIdx.x;
    int tok = p & (NTOK - 1);
    int sel = p >> 12;
    const float* gma = sel ? g1 : g0;
    const float* bta = sel ? b1 : b0;
    size_t base = (size_t)tok * 2048 + sel * 1024;
    int tid = threadIdx.x;
    int c0 = tid * 4;
    __shared__ float red[2][8];
    __half2 h0 = ((const __half2*)(Xin + base + c0))[0];
    __half2 h1 = ((const __half2*)(Xin + base + c0))[1];
    float vv[4] = {__half2float(h0.x), __half2float(h0.y),
                   __half2float(h1.x), __half2float(h1.y)};
    float s = vv[0] + vv[1] + vv[2] + vv[3];
    float s2 = vv[0]*vv[0] + vv[1]*vv[1] + vv[2]*vv[2] + vv[3]*vv[3];
    #pragma unroll
    for (int o = 16; o; o >>= 1) {
        s  += __shfl_xor_sync(0xffffffffu, s, o);
        s2 += __shfl_xor_sync(0xffffffffu, s2, o);
    }
    if ((tid & 31) == 0) { red[0][tid >> 5] = s; red[1][tid >> 5] = s2; }
    __syncthreads();
    if (tid == 0) {
        float aa = 0.f, c = 0.f;
        for (int i = 0; i < 8; i++) { aa += red[0][i]; c += red[1][i]; }
        red[0][0] = aa; red[1][0] = c;
    }
    __syncthreads();
    float mean = red[0][0] * (1.f / 1024.f);
    float var  = red[1][0] * (1.f / 1024.f) - mean * mean;
    float inv  = rsqrtf(var + 1e-5f);
    float xn[4];
    #pragma unroll
    for (int j = 0; j < 4; j++) {
        int c = c0 + j;
        float x = (vv[j] - mean) * inv * gma[c] + bta[c];
        xn[j] = x * (1.f / (1.f + __expf(-x)));
    }
    ((__half2*)(Yout + base + c0))[0] =
        __halves2half2(__float2half_rn(xn[0]), __float2half_rn(xn[1]));
    ((__half2*)(Yout + base + c0))[1] =
        __halves2half2(__float2half_rn(xn[2]), __float2half_rn(xn[3]));
}

// ===================== SSM scan (gate pre-silu'd; bc interleaved) ==========
__global__ __launch_bounds__(256) void scan_kernel(
    const float* __restrict__ xz, const float* __restrict__ dt,
    const float* __restrict__ bc, const float* __restrict__ A_log,
    const float* __restrict__ Dp, float* __restrict__ y)
{
    int pair = blockIdx.x * 16 + (threadIdx.x >> 4);
    int n = threadIdx.x & 15;
    int b = pair >> 10;
    int d = pair & 1023;
    float A  = -__expf(A_log[d * 16 + n]);
    float Dd = Dp[d];
    float h = 0.f;
    #pragma unroll 2
    for (int t = 0; t < NT; t++) {
        int p = t * NB + b;
        float dtv = dt[(size_t)p * 1024 + d];
        float xs  = xz[(size_t)p * 2048 + d];
        float gate = 0.f;
        if (n == 0) gate = xz[(size_t)p * 2048 + 1024 + d];
        float2 bc2 = *(const float2*)(bc + (size_t)p * 32 + 2 * n);
        float g = __expf(dtv * A);
        h = fmaf(g, h, dtv * xs * bc2.x);
        float c = h * bc2.y;
        c += __shfl_xor_sync(0xffffffffu, c, 8, 16);
        c += __shfl_xor_sync(0xffffffffu, c, 4, 16);
        c += __shfl_xor_sync(0xffffffffu, c, 2, 16);
        c += __shfl_xor_sync(0xffffffffu, c, 1, 16);
        if (n == 0) {
            y[(size_t)p * 1024 + d] = (c + Dd * xs) * gate;
        }
    }
}

// ===================== softmax + unimix + log ==============================
__global__ __launch_bounds__(256) void softmax_kernel(
    const float* __restrict__ post, float* __restrict__ out)
{
    int idx  = blockIdx.x * 8 + (threadIdx.x >> 5);
    int lane = threadIdx.x & 31;
    int p = idx >> 5, s = idx & 31;
    float v = post[(size_t)p * 1024 + s * 32 + lane];
    float m = v;
    #pragma unroll
    for (int o = 16; o; o >>= 1) m = fmaxf(m, __shfl_xor_sync(0xffffffffu, m, o));
    float e = __expf(v - m);
    float sum = e;
    #pragma unroll
    for (int o = 16; o; o >>= 1) sum += __shfl_xor_sync(0xffffffffu, sum, o);
    float prob = e / sum;
    out[(size_t)p * 3072 + 2048 + s * 32 + lane] =
        logf(0.99f * prob + 0.01f / 32.f + 1e-8f);
}

// ===========================================================================
extern "C" void kernel_launch(void* const* d_in, const int* in_sizes, int n_in,
                              void* d_out, int out_size)
{
    const float* actions = (const float*)d_in[0];
    const float* embeds  = (const float*)d_in[1];
    const float* W_pre   = (const float*)d_in[2];
    const float* b_pre   = (const float*)d_in[3];
    const float* g_pre   = (const float*)d_in[4];
    const float* bb_pre  = (const float*)d_in[5];
    const float* W_emb   = (const float*)d_in[6];
    const float* W_in    = (const float*)d_in[7];
    const float* b_in    = (const float*)d_in[8];
    const float* W_dt    = (const float*)d_in[9];
    const float* b_dt    = (const float*)d_in[10];
    const float* W_B     = (const float*)d_in[11];
    const float* W_C     = (const float*)d_in[12];
    const float* A_log   = (const float*)d_in[13];
    const float* Dp      = (const float*)d_in[14];
    const float* g_out   = (const float*)d_in[15];
    const float* b_out   = (const float*)d_in[16];
    const float* W_pr1   = (const float*)d_in[17];
    const float* b_pr1   = (const float*)d_in[18];
    const float* g_pr    = (const float*)d_in[19];
    const float* bb_pr   = (const float*)d_in[20];
    const float* W_pr2   = (const float*)d_in[21];
    const float* b_pr2   = (const float*)d_in[22];
    const float* W_po1   = (const float*)d_in[23];
    const float* b_po1   = (const float*)d_in[24];
    const float* g_po    = (const float*)d_in[25];
    const float* bb_po   = (const float*)d_in[26];
    const float* W_po2   = (const float*)d_in[27];
    const float* b_po2   = (const float*)d_in[28];
    float* out = (float*)d_out;

    float *ptmp, *pxz, *pdt, *pbc, *py;
    cudaGetSymbolAddress((void**)&ptmp, g_tmp);
    cudaGetSymbolAddress((void**)&pxz,  g_xz);
    cudaGetSymbolAddress((void**)&pdt,  g_dt);
    cudaGetSymbolAddress((void**)&pbc,  g_bc);
    cudaGetSymbolAddress((void**)&py,   g_y);
    __half *pemb, *px, *pss, *pde, *ph1, *ph2;
    cudaGetSymbolAddress((void**)&pemb, a_emb);
    cudaGetSymbolAddress((void**)&px,  a_x);
    cudaGetSymbolAddress((void**)&pss, a_ssm);
    cudaGetSymbolAddress((void**)&pde, a_det);
    cudaGetSymbolAddress((void**)&ph1, a_h1);
    cudaGetSymbolAddress((void**)&ph2, a_h2);
    __half *wE, *wI, *wD, *wP1, *wP2, *wO1, *wO2;
    cudaGetSymbolAddress((void**)&wE, wt_emb);
    cudaGetSymbolAddress((void**)&wI, wt_in);
    cudaGetSymbolAddress((void**)&wD, wt_dtbc);
    cudaGetSymbolAddress((void**)&wP1, wt_pr1);
    cudaGetSymbolAddress((void**)&wP2, wt_pr2);
    cudaGetSymbolAddress((void**)&wO1, wt_po1);
    cudaGetSymbolAddress((void**)&wO2, wt_po2);

    cudaFuncSetAttribute(gemm_one,  cudaFuncAttributeMaxDynamicSharedMemorySize, GEMM_SMEM);
    cudaFuncSetAttribute(gemm_dual, cudaFuncAttributeMaxDynamicSharedMemorySize, GEMM_SMEM);

    const int BIG = 1 << 30;
    dim3 blk(256);
    dim3 gblk(256);
    dim3 wb(32, 8);

    // WSeg: {W, H, srcN, dstK, koff}; each segment converts a 1024x1024 block.
    WSegs ws;
    ws.s[0] = {W_emb,             wE,              1024, 1024, 0};
    ws.s[1] = {W_dt,              wD,              1024, 1024, 0};
    ws.s[2] = {W_pr1,             wP1,             1024, 1024, 0};
    ws.s[3] = {W_pr2,             wP2,             1024, 1024, 0};
    ws.s[4] = {W_po2,             wO2,             1024, 1024, 0};
    // W_in [K=1024, N=2048] -> Wt [2048, 1024]: split along N (rows of Wt)
    ws.s[5] = {W_in,              wI,              2048, 1024, 0};
    ws.s[6] = {W_in + 1024,       wI + 1024*1024,  2048, 1024, 0};
    // W_po1 [K=2048, N=1024] -> Wt [1024, 2048]: split along K (cols of Wt)
    ws.s[7] = {W_po1,             wO1,             1024, 2048, 0};
    ws.s[8] = {W_po1 + 1024*1024, wO1,             1024, 2048, 1024};

    // 0,1,2 then gemm at capture index 3
    aconv_kernel<<<NTOK, blk>>>(embeds, pemb);                              // 0
    pre_kernel<<<NTOK, blk>>>(actions, W_pre, b_pre, g_pre, bb_pre, ptmp);  // 1
    wconv_multi<<<dim3(32, 32, 9), wb>>>(ws);                               // 2

    // 3: x = emb @ W_emb + x_pre -> fp16   (grid 8x16 = 128 CTAs, 1 wave)
    GemmArgs ax = {pemb, 1024, pemb, 1024, wE, nullptr, 0,
                   ptmp, 1024, nullptr, 0, 0, px, 1024, nullptr, 1024, 0};
    gemm_one<<<dim3(8, 16), gblk, GEMM_SMEM>>>(ax);

    bcconv_kernel<<<128, blk>>>(W_B, W_C, wD);                              // 4

    // 5: xz = x @ W_in + b_in -> fp32 [x_ssm | silu(gate)] + fp16 x_ssm
    GemmArgs axz = {px, BIG, px, 1024, wI, b_in, 2048,
                    nullptr, 0, pxz, 2048, BIG, pss, 1024, nullptr, 1024, 2};
    gemm_one<<<dim3(16, 16), gblk, GEMM_SMEM>>>(axz);

    // 6: dt|bc = x_ssm @ [W_dt | W_B,W_C interleaved]  (N=1152)
    GemmArgs adt = {pss, BIG, pss, 1024, wD, b_dt, 1024,
                    nullptr, 0, pdt, 1024, 1024, nullptr, 0, pbc, 1024, 3};
    gemm_one<<<dim3(9, 16), gblk, GEMM_SMEM>>>(adt);

    // 7: scan
    scan_kernel<<<512, blk>>>(pxz, pdt, pbc, A_log, Dp, py);
    // 8: deter = LN(y) -> out[:,0:1024] + fp16
    ln_kernel<<<NTOK, blk>>>(py, g_out, b_out, out, 3072, pde, 0);

    // 9: dual pr1 / po1 -> a_h1 fp16 [4096,2048]
    GemmArgs ap1 = {pde, BIG, pde, 1024, wP1, b_pr1, 1024,
                    nullptr, 0, nullptr, 0, 0, ph1, 2048, nullptr, 1024, 0};
    GemmArgs ao1 = {pde, 1024, pemb, 1024, wO1, b_po1, 1024,
                    nullptr, 0, nullptr, 0, 0, ph1 + 1024, 2048, nullptr, 2048, 0};
    gemm_dual<<<dim3(8, 16, 2), gblk, GEMM_SMEM>>>(ap1, ao1);

    // 10: batched head lnsilu (fp16 in/out)
    ln16_kernel<<<2 * NTOK, blk>>>(ph1, g_pr, bb_pr, g_po, bb_po, ph2);

    // 11: dual pr2 -> out[:,1024:2048], po2 -> ptmp
    GemmArgs ap2 = {ph2, BIG, ph2, 2048, wP2, b_pr2, 1024,
                    nullptr, 0, out + 1024, 3072, BIG, nullptr, 0, nullptr, 1024, 0};
    GemmArgs ao2 = {ph2 + 1024, BIG, ph2 + 1024, 2048, wO2, b_po2, 1024,
                    nullptr, 0, ptmp, 1024, BIG, nullptr, 0, nullptr, 1024, 0};
    gemm_dual<<<dim3(8, 16, 2), gblk, GEMM_SMEM>>>(ap2, ao2);

    // 12: softmax -> out[:, 2048:3072]
    softmax_kernel<<<NTOK * 32 / 8, blk>>>(ptmp, out);
}

// round 15
// speedup vs baseline: 1.1312x; 1.1312x over previous
#include <cuda_runtime.h>
#include <cuda_fp16.h>
#include <math.h>
#include <stdint.h>

#define NB 8
#define NT 512
#define NTOK 4096

// ===================== helpers =============================================
__device__ __forceinline__ uint32_t smem_to_u32(const void* p) {
    uint32_t a;
    asm("{ .reg .u64 t; cvta.to.shared.u64 t, %1; cvt.u32.u64 %0, t; }" : "=r"(a) : "l"(p));
    return a;
}
__device__ __forceinline__ void cp16(uint32_t s, const void* g) {
    asm volatile("cp.async.cg.shared.global [%0], [%1], 16;" :: "r"(s), "l"(g));
}
#define CP_COMMIT() asm volatile("cp.async.commit_group;" ::: "memory")
#define CP_WAIT(n)  asm volatile("cp.async.wait_group %0;" :: "n"(n) : "memory")

__device__ __forceinline__ void ldm4(uint32_t* r, uint32_t addr) {
    asm volatile("ldmatrix.sync.aligned.m8n8.x4.shared.b16 {%0,%1,%2,%3}, [%4];"
        : "=r"(r[0]), "=r"(r[1]), "=r"(r[2]), "=r"(r[3]) : "r"(addr));
}
__device__ __forceinline__ void mma16816(float* c, const uint32_t* a, const uint32_t* b) {
    asm volatile("mma.sync.aligned.m16n8k16.row.col.f32.f16.f16.f32 "
        "{%0,%1,%2,%3}, {%4,%5,%6,%7}, {%8,%9}, {%0,%1,%2,%3};"
        : "+f"(c[0]), "+f"(c[1]), "+f"(c[2]), "+f"(c[3])
        : "r"(a[0]), "r"(a[1]), "r"(a[2]), "r"(a[3]), "r"(b[0]), "r"(b[1]));
}

// ===================== device scratch ======================================
__device__ float g_tmp[NTOK * 1024];
__device__ float g_xz [NTOK * 2048];   // [x_ssm | silu(gate)]
__device__ float g_dt [NTOK * 1024];
__device__ float g_bc [NTOK * 32];     // interleaved: (B_n, C_n) pairs
__device__ float g_y  [NTOK * 1024];

__device__ __half a_emb[NTOK*1024];
__device__ __half a_x  [NTOK*1024];
__device__ __half a_ssm[NTOK*1024];
__device__ __half a_det[NTOK*1024];
__device__ __half a_h1 [NTOK*2048];    // [pr1 hidden | po1 hidden]
__device__ __half a_h2 [NTOK*2048];    // after lnsilu

// Weights: single fp16, transposed [N,K]
__device__ __half wt_emb [1024*1024];
__device__ __half wt_in  [2048*1024];
__device__ __half wt_dtbc[1152*1024];  // dt rows 0-1023, B/C 1024-1055, zeros above
__device__ __half wt_pr1 [1024*1024];
__device__ __half wt_pr2 [1024*1024];
__device__ __half wt_po1 [1024*2048];  // [N=1024, K=2048]
__device__ __half wt_po2 [1024*1024];

// ===================== HMMA GEMM (single-pass fp16) ========================
// Tile 128(M)x128(N), 4 warps (warp tile 64x64), BK=64, 3 stages, 2 CTAs/SM.
// Halved stage count vs BK=32 — per-stage fixed cost (CP_WAIT/barrier) paid
// 16x instead of 32x for K=1024. 144B-padded rows stay ldmatrix conflict-free
// (144*i mod 128 = 16i pattern). act: 0 none, 1 softplus, 2 silu cols>=1024,
// 3 dt|bc split. Stage: A 128x144 @ +0, B 128x144 @ +18432.
#define STG_BYTES 36864
#define GEMM_SMEM (3*STG_BYTES + 512)

struct GemmArgs {
    const __half* A0; int K0;          // A cols [0,K0) from A0, rest from A1
    const __half* A1;
    int lda;
    const __half* B;
    const float* bias; int biasN;
    const float* addend; int ldadd;
    float* C; int ldc; int nvalid;
    __half* Chi; int ldhl;
    float* bc;                          // act==3 target for cols 1024-1055
    int K; int act;
};

__device__ __forceinline__ void gemm_impl(const GemmArgs a, char* smem)
{
    const uint32_t sb = smem_to_u32(smem);
    const int tid = threadIdx.x;
    const int lane = tid & 31, w = tid >> 5;
    const int bm = blockIdx.y * 128;
    const int bn = blockIdx.x * 128;
    const int wm = (w & 1) * 64;
    const int wn = (w >> 1) * 64;
    float* sbias = (float*)(smem + 3 * STG_BYTES);
    if (tid < 128) sbias[tid] = (a.bias && bn + tid < a.biasN) ? a.bias[bn + tid] : 0.f;

    const int nst = a.K >> 6;

    auto load_stage = [&](int s) {
        const uint32_t dst = sb + (uint32_t)(s % 3) * STG_BYTES;
        const int kglob = s << 6;
        #pragma unroll
        for (int j = 0; j < 16; j++) {
            int q = tid + (j << 7);          // 0..2047
            int op = q >> 10;                // 0:A 1:B
            int row = (q >> 3) & 127;
            int kc = q & 7;
            uint32_t d = dst + (uint32_t)op * 18432u + (uint32_t)(row * 144 + kc * 16);
            const __half* src;
            if (op == 0) {
                int col = kglob + kc * 8;
                const __half* base = a.A0;
                if (col >= a.K0) { base = a.A1; col -= a.K0; }
                src = base + (size_t)(bm + row) * a.lda + col;
            } else {
                src = a.B + (size_t)(bn + row) * a.K + kglob + kc * 8;
            }
            cp16(d, src);
        }
        CP_COMMIT();
    };

    load_stage(0); load_stage(1);

    float acc[4][8][4] = {};

    for (int s = 0; s < nst; s++) {
        CP_WAIT(1);
        __syncthreads();
        // prefetch s+2 BEFORE compute: buffer (s+2)%3 == (s-1)%3, whose readers
        // (compute(s-1)) all finished before the barrier above.
        if (s + 2 < nst) load_stage(s + 2); else CP_COMMIT();
        const uint32_t sA = sb + (uint32_t)(s % 3) * STG_BYTES;
        #pragma unroll
        for (int kk = 0; kk < 4; kk++) {
            const int kloc = kk * 16;
            uint32_t ah[4][4], bb[4][4];
            #pragma unroll
            for (int mi = 0; mi < 4; mi++) {
                uint32_t ad = sA
                    + (uint32_t)((wm + mi * 16 + (lane & 15)) * 144)
                    + (uint32_t)((kloc + ((lane >> 4) << 3)) * 2);
                ldm4(ah[mi], ad);
            }
            #pragma unroll
            for (int nj = 0; nj < 4; nj++) {
                uint32_t bd = sA + 18432u
                    + (uint32_t)((wn + nj * 16 + ((lane >> 4) << 3) + (lane & 7)) * 144)
                    + (uint32_t)((kloc + ((lane >> 3) & 1) * 8) * 2);
                ldm4(bb[nj], bd);
            }
            #pragma unroll
            for (int mi = 0; mi < 4; mi++)
                #pragma unroll
                for (int ns = 0; ns < 8; ns++)
                    mma16816(acc[mi][ns], ah[mi], &bb[ns >> 1][(ns & 1) * 2]);
        }
    }

    // ---- epilogue ----
    const int g = lane >> 2, cc = (lane & 3) * 2;
    const bool dohl = (a.Chi != nullptr) && (bn < a.ldhl);
    #pragma unroll
    for (int mi = 0; mi < 4; mi++) {
        #pragma unroll
        for (int r = 0; r < 2; r++) {
            const int m = bm + wm + mi * 16 + g + r * 8;
            #pragma unroll
            for (int ns = 0; ns < 8; ns++) {
                const int ncol = wn + ns * 8 + cc;
                const int n = bn + ncol;
                float v0 = acc[mi][ns][r * 2 + 0] + sbias[ncol];
                float v1 = acc[mi][ns][r * 2 + 1] + sbias[ncol + 1];
                if (a.act == 3) {
                    if (n < 1024) {
                        v0 = fmaxf(v0, 0.f) + log1pf(__expf(-fabsf(v0)));
                        v1 = fmaxf(v1, 0.f) + log1pf(__expf(-fabsf(v1)));
                        *(float2*)(a.C + (size_t)m * a.ldc + n) = make_float2(v0, v1);
                    } else if (n < 1056) {
                        *(float2*)(a.bc + (size_t)m * 32 + (n - 1024)) = make_float2(v0, v1);
                    }
                    continue;
                }
                if (a.addend) {
                    float2 ad = *(const float2*)(a.addend + (size_t)m * a.ldadd + n);
                    v0 += ad.x; v1 += ad.y;
                }
                if (a.act == 1) {
                    v0 = fmaxf(v0, 0.f) + log1pf(__expf(-fabsf(v0)));
                    v1 = fmaxf(v1, 0.f) + log1pf(__expf(-fabsf(v1)));
                } else if (a.act == 2 && n >= 1024) {
                    v0 = v0 * (1.f / (1.f + __expf(-v0)));
                    v1 = v1 * (1.f / (1.f + __expf(-v1)));
                }
                if (a.C && n < a.nvalid)
                    *(float2*)(a.C + (size_t)m * a.ldc + n) = make_float2(v0, v1);
                if (dohl) {
                    *(__half2*)(a.Chi + (size_t)m * a.ldhl + n) =
                        __halves2half2(__float2half_rn(v0), __float2half_rn(v1));
                }
            }
        }
    }
}

__global__ __launch_bounds__(128, 2) void gemm_one(GemmArgs a) {
    extern __shared__ char smem[];
    gemm_impl(a, smem);
}
__global__ __launch_bounds__(128, 2) void gemm_dual(GemmArgs a0, GemmArgs a1) {
    extern __shared__ char smem[];
    gemm_impl(blockIdx.z ? a1 : a0, smem);
}

// ===================== batched weight transpose -> fp16 ====================
// Transposes a 1024(K) x 1024(N) block of W[.., srcN] into Wt[N, dstK]+koff.
struct WSeg { const float* W; __half* H; int srcN; int dstK; int koff; };
struct WSegs { WSeg s[9]; };
__global__ __launch_bounds__(256) void wconv_multi(WSegs ws)
{
    __shared__ float s[32][33];
    const WSeg seg = ws.s[blockIdx.z];
    const int tx = threadIdx.x, ty = threadIdx.y;
    const int n0 = blockIdx.x * 32, k0 = blockIdx.y * 32;
    #pragma unroll
    for (int j = 0; j < 4; j++)
        s[ty + j * 8][tx] = seg.W[(size_t)(k0 + ty + j * 8) * seg.srcN + n0 + tx];
    __syncthreads();
    #pragma unroll
    for (int j = 0; j < 4; j++) {
        float v = s[tx][ty + j * 8];
        size_t o = (size_t)(n0 + ty + j * 8) * seg.dstK + seg.koff + k0 + tx;
        seg.H[o] = __float2half_rn(v);
    }
}

// ===================== pack W_B|W_C interleaved into wt_dtbc rows 1024+ ====
__global__ __launch_bounds__(256) void bcconv_kernel(
    const float* __restrict__ WB, const float* __restrict__ WC,
    __half* __restrict__ H)
{
    int id = blockIdx.x * 256 + threadIdx.x;   // 32768 total
    int j = id & 31, k = id >> 5;
    float v = (j & 1) ? WC[k * 16 + (j >> 1)] : WB[k * 16 + (j >> 1)];
    H[(size_t)(1024 + j) * 1024 + k] = __float2half_rn(v);
}

// ===================== embeds: [B,T]->[T,B] gather + fp16 ==================
__global__ __launch_bounds__(256) void aconv_kernel(
    const float* __restrict__ X, __half* __restrict__ H)
{
    const int p = blockIdx.x;
    const int src = (p & 7) * NT + (p >> 3);
    const int c = threadIdx.x * 4;
    float4 v = *(const float4*)(X + (size_t)src * 1024 + c);
    ((__half2*)(H + (size_t)p * 1024 + c))[0] =
        __halves2half2(__float2half_rn(v.x), __float2half_rn(v.y));
    ((__half2*)(H + (size_t)p * 1024 + c))[1] =
        __halves2half2(__float2half_rn(v.z), __float2half_rn(v.w));
}

// ===================== stage 0: lnsilu(actions @ W_pre + b) -> fp32 ========
__global__ __launch_bounds__(256) void pre_kernel(
    const float* __restrict__ actions, const float* __restrict__ W_pre,
    const float* __restrict__ b_pre, const float* __restrict__ g_pre,
    const float* __restrict__ bb_pre, float* __restrict__ xout)
{
    int p = blockIdx.x;
    int t = p >> 3, b = p & 7;
    __shared__ float sa[32];
    __shared__ float red[2][8];
    int tid = threadIdx.x;
    if (tid < 32) sa[tid] = actions[(size_t)(b * NT + t) * 32 + tid];
    __syncthreads();
    int c0 = tid * 4;
    float4 acc = *(const float4*)(b_pre + c0);
    #pragma unroll 8
    for (int k = 0; k < 32; k++) {
        float aa = sa[k];
        float4 wv = *(const float4*)(W_pre + (size_t)k * 1024 + c0);
        acc.x = fmaf(aa, wv.x, acc.x); acc.y = fmaf(aa, wv.y, acc.y);
        acc.z = fmaf(aa, wv.z, acc.z); acc.w = fmaf(aa, wv.w, acc.w);
    }
    float s  = acc.x + acc.y + acc.z + acc.w;
    float s2 = acc.x*acc.x + acc.y*acc.y + acc.z*acc.z + acc.w*acc.w;
    #pragma unroll
    for (int o = 16; o; o >>= 1) {
        s  += __shfl_xor_sync(0xffffffffu, s, o);
        s2 += __shfl_xor_sync(0xffffffffu, s2, o);
    }
    if ((tid & 31) == 0) { red[0][tid >> 5] = s; red[1][tid >> 5] = s2; }
    __syncthreads();
    if (tid == 0) {
        float aa = 0.f, c = 0.f;
        for (int i = 0; i < 8; i++) { aa += red[0][i]; c += red[1][i]; }
        red[0][0] = aa; red[1][0] = c;
    }
    __syncthreads();
    float mean = red[0][0] * (1.f / 1024.f);
    float var  = red[1][0] * (1.f / 1024.f) - mean * mean;
    float inv  = rsqrtf(var + 1e-5f);
    float vv[4] = {acc.x, acc.y, acc.z, acc.w};
    #pragma unroll
    for (int j = 0; j < 4; j++) {
        int c = c0 + j;
        float xn = (vv[j] - mean) * inv * g_pre[c] + bb_pre[c];
        xn = xn * (1.f / (1.f + __expf(-xn)));
        xout[(size_t)p * 1024 + c] = xn;
    }
}

// ===================== LayerNorm fp32-in -> fp32 + fp16 ====================
__global__ __launch_bounds__(256) void ln_kernel(
    const float* __restrict__ X,
    const float* __restrict__ gma, const float* __restrict__ bta,
    float* __restrict__ Y, int ldy,
    __half* __restrict__ H, int dosilu)
{
    int p = blockIdx.x;
    int tid = threadIdx.x;
    int c0 = tid * 4;
    __shared__ float red[2][8];
    float4 v = *(const float4*)(X + (size_t)p * 1024 + c0);
    float s  = v.x + v.y + v.z + v.w;
    float s2 = v.x*v.x + v.y*v.y + v.z*v.z + v.w*v.w;
    #pragma unroll
    for (int o = 16; o; o >>= 1) {
        s  += __shfl_xor_sync(0xffffffffu, s, o);
        s2 += __shfl_xor_sync(0xffffffffu, s2, o);
    }
    if ((tid & 31) == 0) { red[0][tid >> 5] = s; red[1][tid >> 5] = s2; }
    __syncthreads();
    if (tid == 0) {
        float aa = 0.f, c = 0.f;
        for (int i = 0; i < 8; i++) { aa += red[0][i]; c += red[1][i]; }
        red[0][0] = aa; red[1][0] = c;
    }
    __syncthreads();
    float mean = red[0][0] * (1.f / 1024.f);
    float var  = red[1][0] * (1.f / 1024.f) - mean * mean;
    float inv  = rsqrtf(var + 1e-5f);
    float vv[4] = {v.x, v.y, v.z, v.w};
    float xn[4];
    #pragma unroll
    for (int j = 0; j < 4; j++) {
        int c = c0 + j;
        float x = (vv[j] - mean) * inv * gma[c] + bta[c];
        if (dosilu) x = x * (1.f / (1.f + __expf(-x)));
        xn[j] = x;
    }
    if (Y) {
        #pragma unroll
        for (int j = 0; j < 4; j++) Y[(size_t)p * ldy + c0 + j] = xn[j];
    }
    if (H) {
        ((__half2*)(H + (size_t)p * 1024 + c0))[0] =
            __halves2half2(__float2half_rn(xn[0]), __float2half_rn(xn[1]));
        ((__half2*)(H + (size_t)p * 1024 + c0))[1] =
            __halves2half2(__float2half_rn(xn[2]), __float2half_rn(xn[3]));
    }
}

// ===================== batched head LN: fp16 in/out, +silu =================
__global__ __launch_bounds__(256) void ln16_kernel(
    const __half* __restrict__ Xin,
    const float* __restrict__ g0, const float* __restrict__ b0,
    const float* __restrict__ g1, const float* __restrict__ b1,
    __half* __restrict__ Yout)
{
    int p = blockIdx.x;
    int tok = p & (NTOK - 1);
    int sel = p >> 12;
    const float* gma = sel ? g1 : g0;
    const float* bta = sel ? b1 : b0;
    size_t base = (size_t)tok * 2048 + sel * 1024;
    int tid = threadIdx.x;
    int c0 = tid * 4;
    __shared__ float red[2][8];
    __half2 h0 = ((const __half2*)(Xin + base + c0))[0];
    __half2 h1 = ((const __half2*)(Xin + base + c0))[1];
    float vv[4] = {__half2float(h0.x), __half2float(h0.y),
                   __half2float(h1.x), __half2float(h1.y)};
    float s = vv[0] + vv[1] + vv[2] + vv[3];
    float s2 = vv[0]*vv[0] + vv[1]*vv[1] + vv[2]*vv[2] + vv[3]*vv[3];
    #pragma unroll
    for (int o = 16; o; o >>= 1) {
        s  += __shfl_xor_sync(0xffffffffu, s, o);
        s2 += __shfl_xor_sync(0xffffffffu, s2, o);
    }
    if ((tid & 31) == 0) { red[0][tid >> 5] = s; red[1][tid >> 5] = s2; }
    __syncthreads();
    if (tid == 0) {
        float aa = 0.f, c = 0.f;
        for (int i = 0; i < 8; i++) { aa += red[0][i]; c += red[1][i]; }
        red[0][0] = aa; red[1][0] = c;
    }
    __syncthreads();
    float mean = red[0][0] * (1.f / 1024.f);
    float var  = red[1][0] * (1.f / 1024.f) - mean * mean;
    float inv  = rsqrtf(var + 1e-5f);
    float xn[4];
    #pragma unroll
    for (int j = 0; j < 4; j++) {
        int c = c0 + j;
        float x = (vv[j] - mean) * inv * gma[c] + bta[c];
        xn[j] = x * (1.f / (1.f + __expf(-x)));
    }
    ((__half2*)(Yout + base + c0))[0] =
        __halves2half2(__float2half_rn(xn[0]), __float2half_rn(xn[1]));
    ((__half2*)(Yout + base + c0))[1] =
        __halves2half2(__float2half_rn(xn[2]), __float2half_rn(xn[3]));
}

// ===================== SSM scan (gate pre-silu'd; bc interleaved) ==========
__global__ __launch_bounds__(256) void scan_kernel(
    const float* __restrict__ xz, const float* __restrict__ dt,
    const float* __restrict__ bc, const float* __restrict__ A_log,
    const float* __restrict__ Dp, float* __restrict__ y)
{
    int pair = blockIdx.x * 16 + (threadIdx.x >> 4);
    int n = threadIdx.x & 15;
    int b = pair >> 10;
    int d = pair & 1023;
    float A  = -__expf(A_log[d * 16 + n]);
    float Dd = Dp[d];
    float h = 0.f;
    #pragma unroll 2
    for (int t = 0; t < NT; t++) {
        int p = t * NB + b;
        float dtv = dt[(size_t)p * 1024 + d];
        float xs  = xz[(size_t)p * 2048 + d];
        float gate = 0.f;
        if (n == 0) gate = xz[(size_t)p * 2048 + 1024 + d];
        float2 bc2 = *(const float2*)(bc + (size_t)p * 32 + 2 * n);
        float g = __expf(dtv * A);
        h = fmaf(g, h, dtv * xs * bc2.x);
        float c = h * bc2.y;
        c += __shfl_xor_sync(0xffffffffu, c, 8, 16);
        c += __shfl_xor_sync(0xffffffffu, c, 4, 16);
        c += __shfl_xor_sync(0xffffffffu, c, 2, 16);
        c += __shfl_xor_sync(0xffffffffu, c, 1, 16);
        if (n == 0) {
            y[(size_t)p * 1024 + d] = (c + Dd * xs) * gate;
        }
    }
}

// ===================== softmax + unimix + log ==============================
__global__ __launch_bounds__(256) void softmax_kernel(
    const float* __restrict__ post, float* __restrict__ out)
{
    int idx  = blockIdx.x * 8 + (threadIdx.x >> 5);
    int lane = threadIdx.x & 31;
    int p = idx >> 5, s = idx & 31;
    float v = post[(size_t)p * 1024 + s * 32 + lane];
    float m = v;
    #pragma unroll
    for (int o = 16; o; o >>= 1) m = fmaxf(m, __shfl_xor_sync(0xffffffffu, m, o));
    float e = __expf(v - m);
    float sum = e;
    #pragma unroll
    for (int o = 16; o; o >>= 1) sum += __shfl_xor_sync(0xffffffffu, sum, o);
    float prob = e / sum;
    out[(size_t)p * 3072 + 2048 + s * 32 + lane] =
        logf(0.99f * prob + 0.01f / 32.f + 1e-8f);
}

// ===========================================================================
extern "C" void kernel_launch(void* const* d_in, const int* in_sizes, int n_in,
                              void* d_out, int out_size)
{
    const float* actions = (const float*)d_in[0];
    const float* embeds  = (const float*)d_in[1];
    const float* W_pre   = (const float*)d_in[2];
    const float* b_pre   = (const float*)d_in[3];
    const float* g_pre   = (const float*)d_in[4];
    const float* bb_pre  = (const float*)d_in[5];
    const float* W_emb   = (const float*)d_in[6];
    const float* W_in    = (const float*)d_in[7];
    const float* b_in    = (const float*)d_in[8];
    const float* W_dt    = (const float*)d_in[9];
    const float* b_dt    = (const float*)d_in[10];
    const float* W_B     = (const float*)d_in[11];
    const float* W_C     = (const float*)d_in[12];
    const float* A_log   = (const float*)d_in[13];
    const float* Dp      = (const float*)d_in[14];
    const float* g_out   = (const float*)d_in[15];
    const float* b_out   = (const float*)d_in[16];
    const float* W_pr1   = (const float*)d_in[17];
    const float* b_pr1   = (const float*)d_in[18];
    const float* g_pr    = (const float*)d_in[19];
    const float* bb_pr   = (const float*)d_in[20];
    const float* W_pr2   = (const float*)d_in[21];
    const float* b_pr2   = (const float*)d_in[22];
    const float* W_po1   = (const float*)d_in[23];
    const float* b_po1   = (const float*)d_in[24];
    const float* g_po    = (const float*)d_in[25];
    const float* bb_po   = (const float*)d_in[26];
    const float* W_po2   = (const float*)d_in[27];
    const float* b_po2   = (const float*)d_in[28];
    float* out = (float*)d_out;

    float *ptmp, *pxz, *pdt, *pbc, *py;
    cudaGetSymbolAddress((void**)&ptmp, g_tmp);
    cudaGetSymbolAddress((void**)&pxz,  g_xz);
    cudaGetSymbolAddress((void**)&pdt,  g_dt);
    cudaGetSymbolAddress((void**)&pbc,  g_bc);
    cudaGetSymbolAddress((void**)&py,   g_y);
    __half *pemb, *px, *pss, *pde, *ph1, *ph2;
    cudaGetSymbolAddress((void**)&pemb, a_emb);
    cudaGetSymbolAddress((void**)&px,  a_x);
    cudaGetSymbolAddress((void**)&pss, a_ssm);
    cudaGetSymbolAddress((void**)&pde, a_det);
    cudaGetSymbolAddress((void**)&ph1, a_h1);
    cudaGetSymbolAddress((void**)&ph2, a_h2);
    __half *wE, *wI, *wD, *wP1, *wP2, *wO1, *wO2;
    cudaGetSymbolAddress((void**)&wE, wt_emb);
    cudaGetSymbolAddress((void**)&wI, wt_in);
    cudaGetSymbolAddress((void**)&wD, wt_dtbc);
    cudaGetSymbolAddress((void**)&wP1, wt_pr1);
    cudaGetSymbolAddress((void**)&wP2, wt_pr2);
    cudaGetSymbolAddress((void**)&wO1, wt_po1);
    cudaGetSymbolAddress((void**)&wO2, wt_po2);

    cudaFuncSetAttribute(gemm_one,  cudaFuncAttributeMaxDynamicSharedMemorySize, GEMM_SMEM);
    cudaFuncSetAttribute(gemm_dual, cudaFuncAttributeMaxDynamicSharedMemorySize, GEMM_SMEM);

    const int BIG = 1 << 30;
    dim3 blk(256);
    dim3 gblk(128);
    dim3 wb(32, 8);

    // WSeg: {W, H, srcN, dstK, koff}; each segment converts a 1024x1024 block.
    WSegs ws;
    ws.s[0] = {W_emb,             wE,              1024, 1024, 0};
    ws.s[1] = {W_dt,              wD,              1024, 1024, 0};
    ws.s[2] = {W_pr1,             wP1,             1024, 1024, 0};
    ws.s[3] = {W_pr2,             wP2,             1024, 1024, 0};
    ws.s[4] = {W_po2,             wO2,             1024, 1024, 0};
    // W_in [K=1024, N=2048] -> Wt [2048, 1024]: split along N (rows of Wt)
    ws.s[5] = {W_in,              wI,              2048, 1024, 0};
    ws.s[6] = {W_in + 1024,       wI + 1024*1024,  2048, 1024, 0};
    // W_po1 [K=2048, N=1024] -> Wt [1024, 2048]: split along K (cols of Wt)
    ws.s[7] = {W_po1,             wO1,             1024, 2048, 0};
    ws.s[8] = {W_po1 + 1024*1024, wO1,             1024, 2048, 1024};

    // 0,1,2 then gemm at capture index 3
    aconv_kernel<<<NTOK, blk>>>(embeds, pemb);                              // 0
    pre_kernel<<<NTOK, blk>>>(actions, W_pre, b_pre, g_pre, bb_pre, ptmp);  // 1
    wconv_multi<<<dim3(32, 32, 9), wb>>>(ws);                               // 2

    // 3: x = emb @ W_emb + x_pre -> fp16
    GemmArgs ax = {pemb, 1024, pemb, 1024, wE, nullptr, 0,
                   ptmp, 1024, nullptr, 0, 0, px, 1024, nullptr, 1024, 0};
    gemm_one<<<dim3(8, 32), gblk, GEMM_SMEM>>>(ax);

    bcconv_kernel<<<128, blk>>>(W_B, W_C, wD);                              // 4

    // 5: xz = x @ W_in + b_in -> fp32 [x_ssm | silu(gate)] + fp16 x_ssm
    GemmArgs axz = {px, BIG, px, 1024, wI, b_in, 2048,
                    nullptr, 0, pxz, 2048, BIG, pss, 1024, nullptr, 1024, 2};
    gemm_one<<<dim3(16, 32), gblk, GEMM_SMEM>>>(axz);

    // 6: dt|bc = x_ssm @ [W_dt | W_B,W_C interleaved]  (N=1152)
    GemmArgs adt = {pss, BIG, pss, 1024, wD, b_dt, 1024,
                    nullptr, 0, pdt, 1024, 1024, nullptr, 0, pbc, 1024, 3};
    gemm_one<<<dim3(9, 32), gblk, GEMM_SMEM>>>(adt);

    // 7: scan
    scan_kernel<<<512, blk>>>(pxz, pdt, pbc, A_log, Dp, py);
    // 8: deter = LN(y) -> out[:,0:1024] + fp16
    ln_kernel<<<NTOK, blk>>>(py, g_out, b_out, out, 3072, pde, 0);

    // 9: dual pr1 / po1 -> a_h1 fp16 [4096,2048]
    GemmArgs ap1 = {pde, BIG, pde, 1024, wP1, b_pr1, 1024,
                    nullptr, 0, nullptr, 0, 0, ph1, 2048, nullptr, 1024, 0};
    GemmArgs ao1 = {pde, 1024, pemb, 1024, wO1, b_po1, 1024,
                    nullptr, 0, nullptr, 0, 0, ph1 + 1024, 2048, nullptr, 2048, 0};
    gemm_dual<<<dim3(8, 32, 2), gblk, GEMM_SMEM>>>(ap1, ao1);

    // 10: batched head lnsilu (fp16 in/out)
    ln16_kernel<<<2 * NTOK, blk>>>(ph1, g_pr, bb_pr, g_po, bb_po, ph2);

    // 11: dual pr2 -> out[:,1024:2048], po2 -> ptmp
    GemmArgs ap2 = {ph2, BIG, ph2, 2048, wP2, b_pr2, 1024,
                    nullptr, 0, out + 1024, 3072, BIG, nullptr, 0, nullptr, 1024, 0};
    GemmArgs ao2 = {ph2 + 1024, BIG, ph2 + 1024, 2048, wO2, b_po2, 1024,
                    nullptr, 0, ptmp, 1024, BIG, nullptr, 0, nullptr, 1024, 0};
    gemm_dual<<<dim3(8, 32, 2), gblk, GEMM_SMEM>>>(ap2, ao2);

    // 12: softmax -> out[:, 2048:3072]
    softmax_kernel<<<NTOK * 32 / 8, blk>>>(ptmp, out);
}